// round 13
// baseline (speedup 1.0000x reference)
#include <cuda_runtime.h>
#include <cstdint>
#include <cstddef>

typedef unsigned long long U64;

#define KC 32

// ---------------- persistent device scratch ----------------
__device__ float g_xT[64 * 256 * 64];        // [t][d][b]   4 MB
__device__ float g_h[3 * 2 * 1024 * 64];     // [layer][parity][hcol][b] 1.5 MB
__device__ float g_c[3 * 1024 * 64];         // [layer][hcol][b] 0.75 MB
__device__ float g_outs[64 * 1024 * 64];     // [t][hcol][b] 16 MB

// ---------------- helpers ----------------
__device__ __forceinline__ U64 dupf(float x) {
    U64 r; unsigned u = __float_as_uint(x);
    asm("mov.b64 %0, {%1, %1};" : "=l"(r) : "r"(u));
    return r;
}
__device__ __forceinline__ U64 fma2(U64 a, U64 b, U64 c) {
    U64 d; asm("fma.rn.f32x2 %0, %1, %2, %3;" : "=l"(d) : "l"(a), "l"(b), "l"(c));
    return d;
}
__device__ __forceinline__ void unpk(U64 v, float& lo, float& hi) {
    unsigned a, b;
    asm("mov.b64 {%0, %1}, %2;" : "=r"(a), "=r"(b) : "l"(v));
    lo = __uint_as_float(a); hi = __uint_as_float(b);
}
__device__ __forceinline__ void cpa16(uint32_t s, const void* g) {
    asm volatile("cp.async.cg.shared.global [%0], [%1], 16;" :: "r"(s), "l"(g));
}
__device__ __forceinline__ float sigm(float x) { return 1.f / (1.f + expf(-x)); }

// ---------------- pre-transforms ----------------
// x [b][t][d] -> xT [t][d][b]
__global__ void transpose_x(const float* __restrict__ x, float* __restrict__ xT) {
    int idx = blockIdx.x * 256 + threadIdx.x;    // 64*64*256 = 1,048,576
    int b = idx >> 14, t = (idx >> 8) & 63, d = idx & 255;
    xT[((size_t)t * 256 + d) * 64 + b] = x[idx];
}

// h0/c0 [L][1][1024] broadcast into transposed state buffers (parity 0)
__global__ void init_hc(const float* __restrict__ h0, const float* __restrict__ c0,
                        float* __restrict__ hb, float* __restrict__ cb) {
    int idx = blockIdx.x * 256 + threadIdx.x;    // 3*1024*64 = 196608
    int l = idx >> 16, rem = idx & 65535, k = rem >> 6;
    hb[(size_t)l * 2 * 65536 + rem] = h0[l * 1024 + k];
    cb[(size_t)l * 65536 + rem]     = c0[l * 1024 + k];
}

// ---------------- one LSTM cell stage ----------------
// z[col = g*1024+hcol][row] = sum_k a[k][row] * W[k][col], two k-segments
// (a0/w0 length K0, a1/w1 length 1024). Then full cell update with bias,
// peephole Wc on ALL 4 gates, gate order (f, i, g, o).
// grid 128 CTAs (8 hcols each), 256 threads: thread = 1 of 32 gate-cols x 8 rows.
__global__ void __launch_bounds__(256, 1) lstm_stage(
    const float* __restrict__ a0, const float* __restrict__ w0, int K0,
    const float* __restrict__ a1, const float* __restrict__ w1,
    const float* __restrict__ wc, const float* __restrict__ bias,
    float* __restrict__ cst, float* __restrict__ hout, float* __restrict__ outdup)
{
    __shared__ __align__(16) float As[2][KC][64];   // [k][batch]
    __shared__ __align__(16) float Ws[2][KC][32];   // [k][g*8+hc]
    __shared__ float Zs[32][65];

    const int tid = threadIdx.x;
    const int blk = blockIdx.x;
    const int c  = tid & 31;        // gate-col within CTA: g*8 + hc
    const int rg = tid >> 5;        // row group (8 rows)
    const int nch = (K0 + 1024) >> 5;

    uint32_t sA = (uint32_t)__cvta_generic_to_shared(&As[0][0][0]);
    uint32_t sW = (uint32_t)__cvta_generic_to_shared(&Ws[0][0][0]);

    U64 acc0 = 0, acc1 = 0, acc2 = 0, acc3 = 0;

    auto issue = [&](int ch, int buf) {
        int kb = ch << 5;
        const float* ab; const float* wb;
        if (kb < K0) { ab = a0 + (size_t)kb * 64; wb = w0 + (size_t)kb * 4096; }
        else { int kk = kb - K0; ab = a1 + (size_t)kk * 64; wb = w1 + (size_t)kk * 4096; }
        // A tile: 32k x 64b floats = 512 x 16B chunks -> 2 per thread
        #pragma unroll
        for (int j = 0; j < 2; ++j) {
            int i = tid + j * 256;
            int k = i >> 4, m4 = (i & 15) << 2;
            cpa16(sA + (uint32_t)((buf * KC * 64 + k * 64 + m4) * 4), ab + k * 64 + m4);
        }
        // W tile: per k the 32 cols live in 4 gate segments of 8 floats -> 8 x 16B chunks
        {
            int k = tid >> 3, seg = tid & 7, g = seg >> 1, off = (seg & 1) << 2;
            cpa16(sW + (uint32_t)((buf * KC * 32 + k * 32 + g * 8 + off) * 4),
                  wb + (size_t)k * 4096 + (size_t)g * 1024 + blk * 8 + off);
        }
        asm volatile("cp.async.commit_group;");
    };

    issue(0, 0);
    asm volatile("cp.async.wait_group 0;");
    __syncthreads();

    for (int ch = 0; ch < nch; ++ch) {
        int buf = ch & 1;
        if (ch + 1 < nch) issue(ch + 1, buf ^ 1);
        #pragma unroll
        for (int kk = 0; kk < KC; ++kk) {
            U64 wd = dupf(Ws[buf][kk][c]);
            ulonglong2 av  = *(const ulonglong2*)&As[buf][kk][rg * 8];
            ulonglong2 av2 = *(const ulonglong2*)&As[buf][kk][rg * 8 + 4];
            acc0 = fma2(av.x,  wd, acc0);
            acc1 = fma2(av.y,  wd, acc1);
            acc2 = fma2(av2.x, wd, acc2);
            acc3 = fma2(av2.y, wd, acc3);
        }
        if (ch + 1 < nch) asm volatile("cp.async.wait_group 0;");
        __syncthreads();
    }

    // dump z into smem so each cell's 4 gates can meet in one thread
    {
        float l0, h0v, l1, h1v, l2, h2v, l3, h3v;
        unpk(acc0, l0, h0v); unpk(acc1, l1, h1v);
        unpk(acc2, l2, h2v); unpk(acc3, l3, h3v);
        int rb = rg * 8;
        Zs[c][rb + 0] = l0;  Zs[c][rb + 1] = h0v;
        Zs[c][rb + 2] = l1;  Zs[c][rb + 3] = h1v;
        Zs[c][rb + 4] = l2;  Zs[c][rb + 5] = h2v;
        Zs[c][rb + 6] = l3;  Zs[c][rb + 7] = h3v;
    }
    __syncthreads();

    #pragma unroll
    for (int j = 0; j < 2; ++j) {
        int cell = tid * 2 + j;          // 512 cells = 8 hcols x 64 rows
        int hc = cell >> 6, r = cell & 63;
        int hcol = blk * 8 + hc;
        float zf = Zs[hc][r], zi = Zs[8 + hc][r], zg = Zs[16 + hc][r], zo = Zs[24 + hc][r];
        float cv = cst[hcol * 64 + r];
        float fg = sigm(zf + bias[hcol]          + wc[hcol]        * cv);
        float ig = sigm(zi + bias[1024 + hcol]   + wc[1024 + hcol] * cv);
        float gg = tanhf(zg + bias[2048 + hcol]  + wc[2048 + hcol] * cv);
        float og = sigm(zo + bias[3072 + hcol]   + wc[3072 + hcol] * cv);
        float cn = fg * cv + ig * gg;
        float hv = og * tanhf(cn);
        cst[hcol * 64 + r]  = cn;
        hout[hcol * 64 + r] = hv;
        if (outdup) outdup[hcol * 64 + r] = hv;
    }
}

// ---------------- final projection ----------------
// out[t][b][d] = sigmoid( sum_k outs[t][k][b] * finW[k][d] + finb[d] )
// grid (4 d-quarters, 64 t), 256 threads: thread = 1 of 64 d-cols x 16 rows.
__global__ void __launch_bounds__(256, 1) final_proj(
    const float* __restrict__ outs, const float* __restrict__ W,
    const float* __restrict__ bvec, float* __restrict__ out)
{
    __shared__ __align__(16) float Ash[KC][64];
    __shared__ __align__(16) float Wsh[KC][64];
    const int t = blockIdx.y, dq = blockIdx.x;
    const int tid = threadIdx.x;
    const int dc = tid & 63, rg = tid >> 6;
    const float* abase = outs + (size_t)t * 65536;

    U64 acc[8];
    #pragma unroll
    for (int q = 0; q < 8; ++q) acc[q] = 0;

    for (int kb = 0; kb < 1024; kb += KC) {
        __syncthreads();
        #pragma unroll
        for (int j = 0; j < 2; ++j) {
            int i = tid + j * 256;
            int k = i >> 4, m4 = (i & 15) << 2;
            *(float4*)&Ash[k][m4] = *(const float4*)(abase + (size_t)(kb + k) * 64 + m4);
            *(float4*)&Wsh[k][m4] = *(const float4*)(W + (size_t)(kb + k) * 256 + dq * 64 + m4);
        }
        __syncthreads();
        #pragma unroll
        for (int k = 0; k < KC; ++k) {
            U64 wd = dupf(Wsh[k][dc]);
            const ulonglong2* ap = (const ulonglong2*)&Ash[k][rg * 16];
            #pragma unroll
            for (int q = 0; q < 4; ++q) {
                ulonglong2 u = ap[q];
                acc[2 * q]     = fma2(u.x, wd, acc[2 * q]);
                acc[2 * q + 1] = fma2(u.y, wd, acc[2 * q + 1]);
            }
        }
    }

    int dg = dq * 64 + dc;
    float bb = bvec[dg];
    #pragma unroll
    for (int q = 0; q < 8; ++q) {
        float lo, hi; unpk(acc[q], lo, hi);
        int r0 = rg * 16 + 2 * q;
        out[((size_t)t * 64 + r0)     * 256 + dg] = sigm(lo + bb);
        out[((size_t)t * 64 + r0 + 1) * 256 + dg] = sigm(hi + bb);
    }
}

// ---------------- host driver ----------------
extern "C" void kernel_launch(void* const* d_in, const int* in_sizes, int n_in,
                              void* d_out, int out_size)
{
    const float* x    = (const float*)d_in[0];
    const float* eWx0 = (const float*)d_in[1];
    const float* eWh0 = (const float*)d_in[2];
    const float* eWc0 = (const float*)d_in[3];
    const float* eb0  = (const float*)d_in[4];
    const float* eWx  = (const float*)d_in[5];
    const float* eWh  = (const float*)d_in[6];
    const float* eWc  = (const float*)d_in[7];
    const float* eb   = (const float*)d_in[8];
    const float* dWx  = (const float*)d_in[9];
    const float* dWh  = (const float*)d_in[10];
    const float* dWc  = (const float*)d_in[11];
    const float* db   = (const float*)d_in[12];
    const float* fW   = (const float*)d_in[13];
    const float* fb   = (const float*)d_in[14];
    const float* h0   = (const float*)d_in[15];
    const float* c0   = (const float*)d_in[16];

    float *xT, *hb, *cb, *ob;
    cudaGetSymbolAddress((void**)&xT, g_xT);
    cudaGetSymbolAddress((void**)&hb, g_h);
    cudaGetSymbolAddress((void**)&cb, g_c);
    cudaGetSymbolAddress((void**)&ob, g_outs);

    transpose_x<<<4096, 256>>>(x, xT);
    init_hc<<<768, 256>>>(h0, c0, hb, cb);

    const size_t HS  = 65536;                // 1024 * 64
    const size_t WSZ = 1024ull * 4096;
    auto H = [&](int l, int p) { return hb + ((size_t)l * 2 + p) * HS; };

    int par = 0;
    // -------- encoder: 64 steps x 3 layers --------
    for (int t = 0; t < 64; ++t) {
        const float* xin = xT + (size_t)t * 256 * 64;
        lstm_stage<<<128, 256>>>(xin, eWx0, 256, H(0, par), eWh0,
                                 eWc0, eb0, cb + 0 * HS, H(0, par ^ 1), (float*)0);
        lstm_stage<<<128, 256>>>(H(0, par ^ 1), eWx + 0 * WSZ, 1024, H(1, par), eWh + 0 * WSZ,
                                 eWc + 0 * 4096, eb + 0 * 4096, cb + 1 * HS, H(1, par ^ 1), (float*)0);
        lstm_stage<<<128, 256>>>(H(1, par ^ 1), eWx + 1 * WSZ, 1024, H(2, par), eWh + 1 * WSZ,
                                 eWc + 1 * 4096, eb + 1 * 4096, cb + 2 * HS, H(2, par ^ 1), (float*)0);
        par ^= 1;
    }
    // -------- decoder: 64 steps x 3 layers; layer0 input = previous top h --------
    for (int t = 0; t < 64; ++t) {
        lstm_stage<<<128, 256>>>(H(2, par), dWx + 0 * WSZ, 1024, H(0, par), dWh + 0 * WSZ,
                                 dWc + 0 * 4096, db + 0 * 4096, cb + 0 * HS, H(0, par ^ 1), (float*)0);
        lstm_stage<<<128, 256>>>(H(0, par ^ 1), dWx + 1 * WSZ, 1024, H(1, par), dWh + 1 * WSZ,
                                 dWc + 1 * 4096, db + 1 * 4096, cb + 1 * HS, H(1, par ^ 1), (float*)0);
        lstm_stage<<<128, 256>>>(H(1, par ^ 1), dWx + 2 * WSZ, 1024, H(2, par), dWh + 2 * WSZ,
                                 dWc + 2 * 4096, db + 2 * 4096, cb + 2 * HS, H(2, par ^ 1),
                                 ob + (size_t)t * HS);
        par ^= 1;
    }

    final_proj<<<dim3(4, 64), 256>>>(ob, fW, fb, (float*)d_out);
}

// round 14
// speedup vs baseline: 1.0400x; 1.0400x over previous
#include <cuda_runtime.h>
#include <cstdint>
#include <cstddef>

typedef unsigned long long U64;

#define KC 32

// ---------------- persistent device scratch ----------------
__device__ float g_xT[64 * 256 * 64];        // [t][d][b]   4 MB
__device__ float g_h[3 * 2 * 1024 * 64];     // [layer][parity][hcol][b] 1.5 MB
__device__ float g_c[3 * 1024 * 64];         // [layer][hcol][b] 0.75 MB
__device__ float g_outs[64 * 1024 * 64];     // [t][hcol][b] 16 MB

// ---------------- helpers ----------------
__device__ __forceinline__ U64 dupf(float x) {
    U64 r; unsigned u = __float_as_uint(x);
    asm("mov.b64 %0, {%1, %1};" : "=l"(r) : "r"(u));
    return r;
}
__device__ __forceinline__ U64 fma2(U64 a, U64 b, U64 c) {
    U64 d; asm("fma.rn.f32x2 %0, %1, %2, %3;" : "=l"(d) : "l"(a), "l"(b), "l"(c));
    return d;
}
__device__ __forceinline__ void unpk(U64 v, float& lo, float& hi) {
    unsigned a, b;
    asm("mov.b64 {%0, %1}, %2;" : "=r"(a), "=r"(b) : "l"(v));
    lo = __uint_as_float(a); hi = __uint_as_float(b);
}
__device__ __forceinline__ void cpa16(uint32_t s, const void* g) {
    asm volatile("cp.async.cg.shared.global [%0], [%1], 16;" :: "r"(s), "l"(g));
}
__device__ __forceinline__ float sigm(float x) { return 1.f / (1.f + expf(-x)); }

// ---------------- pre-transforms ----------------
// x [b][t][d] -> xT [t][d][b]
__global__ void transpose_x(const float* __restrict__ x, float* __restrict__ xT) {
    int idx = blockIdx.x * 256 + threadIdx.x;    // 64*64*256 = 1,048,576
    int b = idx >> 14, t = (idx >> 8) & 63, d = idx & 255;
    xT[((size_t)t * 256 + d) * 64 + b] = x[idx];
}

// h0/c0 [L][1][1024] broadcast into transposed state buffers (parity 0)
__global__ void init_hc(const float* __restrict__ h0, const float* __restrict__ c0,
                        float* __restrict__ hb, float* __restrict__ cb) {
    int idx = blockIdx.x * 256 + threadIdx.x;    // 3*1024*64 = 196608
    int l = idx >> 16, rem = idx & 65535, k = rem >> 6;
    hb[(size_t)l * 2 * 65536 + rem] = h0[l * 1024 + k];
    cb[(size_t)l * 65536 + rem]     = c0[l * 1024 + k];
}

// ---------------- one LSTM cell stage ----------------
// z[col = g*1024+hcol][row] = sum_k a[k][row] * W[k][col], two k-segments
// (a0/w0 length K0, a1/w1 length 1024). Then full cell update with bias,
// peephole Wc on ALL 4 gates, gate order (f, i, g, o).
// grid 128 CTAs (8 hcols each), 256 threads: thread = 1 of 32 gate-cols x 8 rows.
// 4-deep cp.async pipeline (~2.5 chunks in flight) to decouple DRAM latency.
__global__ void __launch_bounds__(256, 1) lstm_stage(
    const float* __restrict__ a0, const float* __restrict__ w0, int K0,
    const float* __restrict__ a1, const float* __restrict__ w1,
    const float* __restrict__ wc, const float* __restrict__ bias,
    float* __restrict__ cst, float* __restrict__ hout, float* __restrict__ outdup)
{
    __shared__ __align__(16) float As[4][KC][64];   // [buf][k][batch]  32 KB
    __shared__ __align__(16) float Ws[4][KC][32];   // [buf][k][g*8+hc] 16 KB

    const int tid = threadIdx.x;
    const int blk = blockIdx.x;
    const int c  = tid & 31;        // gate-col within CTA: g*8 + hc
    const int rg = tid >> 5;        // row group (8 rows)
    const int nch = (K0 + 1024) >> 5;

    uint32_t sA = (uint32_t)__cvta_generic_to_shared(&As[0][0][0]);
    uint32_t sW = (uint32_t)__cvta_generic_to_shared(&Ws[0][0][0]);

    U64 acc0 = 0, acc1 = 0, acc2 = 0, acc3 = 0;

    auto issue = [&](int ch, int buf) {
        int kb = ch << 5;
        const float* ab; const float* wb;
        if (kb < K0) { ab = a0 + (size_t)kb * 64; wb = w0 + (size_t)kb * 4096; }
        else { int kk = kb - K0; ab = a1 + (size_t)kk * 64; wb = w1 + (size_t)kk * 4096; }
        // A tile: 32k x 64b floats = 512 x 16B chunks -> 2 per thread
        #pragma unroll
        for (int j = 0; j < 2; ++j) {
            int i = tid + j * 256;
            int k = i >> 4, m4 = (i & 15) << 2;
            cpa16(sA + (uint32_t)((buf * KC * 64 + k * 64 + m4) * 4), ab + k * 64 + m4);
        }
        // W tile: per k the 32 cols live in 4 gate segments of 8 floats -> 8 x 16B chunks
        {
            int k = tid >> 3, seg = tid & 7, g = seg >> 1, off = (seg & 1) << 2;
            cpa16(sW + (uint32_t)((buf * KC * 32 + k * 32 + g * 8 + off) * 4),
                  wb + (size_t)k * 4096 + (size_t)g * 1024 + blk * 8 + off);
        }
        asm volatile("cp.async.commit_group;");
    };

    // prologue: fill 3 pipeline stages
    issue(0, 0); issue(1, 1); issue(2, 2);

    for (int ch = 0; ch < nch; ++ch) {
        // wait until chunk ch's group is complete (allow the newest in-flight ones)
        int allow = nch - 1 - ch;
        if (allow >= 2)      asm volatile("cp.async.wait_group 2;");
        else if (allow == 1) asm volatile("cp.async.wait_group 1;");
        else                 asm volatile("cp.async.wait_group 0;");
        __syncthreads();   // chunk ch visible to all; all warps done reading buf (ch-1)&3

        if (ch + 3 < nch) issue(ch + 3, (ch + 3) & 3);  // reuses buffer of chunk ch-1

        const int buf = ch & 3;
        #pragma unroll
        for (int kk = 0; kk < KC; ++kk) {
            U64 wd = dupf(Ws[buf][kk][c]);
            ulonglong2 av  = *(const ulonglong2*)&As[buf][kk][rg * 8];
            ulonglong2 av2 = *(const ulonglong2*)&As[buf][kk][rg * 8 + 4];
            acc0 = fma2(av.x,  wd, acc0);
            acc1 = fma2(av.y,  wd, acc1);
            acc2 = fma2(av2.x, wd, acc2);
            acc3 = fma2(av2.y, wd, acc3);
        }
    }

    __syncthreads();   // all warps done with As before overlaying Zs on it

    // Zs scratch overlaid on the A pipeline buffers (no longer needed)
    float (*Zs)[65] = (float(*)[65])(&As[0][0][0]);   // [32][65]

    {
        float l0, h0v, l1, h1v, l2, h2v, l3, h3v;
        unpk(acc0, l0, h0v); unpk(acc1, l1, h1v);
        unpk(acc2, l2, h2v); unpk(acc3, l3, h3v);
        int rb = rg * 8;
        Zs[c][rb + 0] = l0;  Zs[c][rb + 1] = h0v;
        Zs[c][rb + 2] = l1;  Zs[c][rb + 3] = h1v;
        Zs[c][rb + 4] = l2;  Zs[c][rb + 5] = h2v;
        Zs[c][rb + 6] = l3;  Zs[c][rb + 7] = h3v;
    }
    __syncthreads();

    #pragma unroll
    for (int j = 0; j < 2; ++j) {
        int cell = tid * 2 + j;          // 512 cells = 8 hcols x 64 rows
        int hc = cell >> 6, r = cell & 63;
        int hcol = blk * 8 + hc;
        float zf = Zs[hc][r], zi = Zs[8 + hc][r], zg = Zs[16 + hc][r], zo = Zs[24 + hc][r];
        float cv = cst[hcol * 64 + r];
        float fg = sigm(zf + bias[hcol]          + wc[hcol]        * cv);
        float ig = sigm(zi + bias[1024 + hcol]   + wc[1024 + hcol] * cv);
        float gg = tanhf(zg + bias[2048 + hcol]  + wc[2048 + hcol] * cv);
        float og = sigm(zo + bias[3072 + hcol]   + wc[3072 + hcol] * cv);
        float cn = fg * cv + ig * gg;
        float hv = og * tanhf(cn);
        cst[hcol * 64 + r]  = cn;
        hout[hcol * 64 + r] = hv;
        if (outdup) outdup[hcol * 64 + r] = hv;
    }
}

// ---------------- final projection ----------------
// out[t][b][d] = sigmoid( sum_k outs[t][k][b] * finW[k][d] + finb[d] )
// grid (4 d-quarters, 64 t), 256 threads: thread = 1 of 64 d-cols x 16 rows.
__global__ void __launch_bounds__(256, 1) final_proj(
    const float* __restrict__ outs, const float* __restrict__ W,
    const float* __restrict__ bvec, float* __restrict__ out)
{
    __shared__ __align__(16) float Ash[KC][64];
    __shared__ __align__(16) float Wsh[KC][64];
    const int t = blockIdx.y, dq = blockIdx.x;
    const int tid = threadIdx.x;
    const int dc = tid & 63, rg = tid >> 6;
    const float* abase = outs + (size_t)t * 65536;

    U64 acc[8];
    #pragma unroll
    for (int q = 0; q < 8; ++q) acc[q] = 0;

    for (int kb = 0; kb < 1024; kb += KC) {
        __syncthreads();
        #pragma unroll
        for (int j = 0; j < 2; ++j) {
            int i = tid + j * 256;
            int k = i >> 4, m4 = (i & 15) << 2;
            *(float4*)&Ash[k][m4] = *(const float4*)(abase + (size_t)(kb + k) * 64 + m4);
            *(float4*)&Wsh[k][m4] = *(const float4*)(W + (size_t)(kb + k) * 256 + dq * 64 + m4);
        }
        __syncthreads();
        #pragma unroll
        for (int k = 0; k < KC; ++k) {
            U64 wd = dupf(Wsh[k][dc]);
            const ulonglong2* ap = (const ulonglong2*)&Ash[k][rg * 16];
            #pragma unroll
            for (int q = 0; q < 4; ++q) {
                ulonglong2 u = ap[q];
                acc[2 * q]     = fma2(u.x, wd, acc[2 * q]);
                acc[2 * q + 1] = fma2(u.y, wd, acc[2 * q + 1]);
            }
        }
    }

    int dg = dq * 64 + dc;
    float bb = bvec[dg];
    #pragma unroll
    for (int q = 0; q < 8; ++q) {
        float lo, hi; unpk(acc[q], lo, hi);
        int r0 = rg * 16 + 2 * q;
        out[((size_t)t * 64 + r0)     * 256 + dg] = sigm(lo + bb);
        out[((size_t)t * 64 + r0 + 1) * 256 + dg] = sigm(hi + bb);
    }
}

// ---------------- host driver ----------------
extern "C" void kernel_launch(void* const* d_in, const int* in_sizes, int n_in,
                              void* d_out, int out_size)
{
    const float* x    = (const float*)d_in[0];
    const float* eWx0 = (const float*)d_in[1];
    const float* eWh0 = (const float*)d_in[2];
    const float* eWc0 = (const float*)d_in[3];
    const float* eb0  = (const float*)d_in[4];
    const float* eWx  = (const float*)d_in[5];
    const float* eWh  = (const float*)d_in[6];
    const float* eWc  = (const float*)d_in[7];
    const float* eb   = (const float*)d_in[8];
    const float* dWx  = (const float*)d_in[9];
    const float* dWh  = (const float*)d_in[10];
    const float* dWc  = (const float*)d_in[11];
    const float* db   = (const float*)d_in[12];
    const float* fW   = (const float*)d_in[13];
    const float* fb   = (const float*)d_in[14];
    const float* h0   = (const float*)d_in[15];
    const float* c0   = (const float*)d_in[16];

    float *xT, *hb, *cb, *ob;
    cudaGetSymbolAddress((void**)&xT, g_xT);
    cudaGetSymbolAddress((void**)&hb, g_h);
    cudaGetSymbolAddress((void**)&cb, g_c);
    cudaGetSymbolAddress((void**)&ob, g_outs);

    transpose_x<<<4096, 256>>>(x, xT);
    init_hc<<<768, 256>>>(h0, c0, hb, cb);

    const size_t HS  = 65536;                // 1024 * 64
    const size_t WSZ = 1024ull * 4096;
    auto H = [&](int l, int p) { return hb + ((size_t)l * 2 + p) * HS; };

    int par = 0;
    // -------- encoder: 64 steps x 3 layers --------
    for (int t = 0; t < 64; ++t) {
        const float* xin = xT + (size_t)t * 256 * 64;
        lstm_stage<<<128, 256>>>(xin, eWx0, 256, H(0, par), eWh0,
                                 eWc0, eb0, cb + 0 * HS, H(0, par ^ 1), (float*)0);
        lstm_stage<<<128, 256>>>(H(0, par ^ 1), eWx + 0 * WSZ, 1024, H(1, par), eWh + 0 * WSZ,
                                 eWc + 0 * 4096, eb + 0 * 4096, cb + 1 * HS, H(1, par ^ 1), (float*)0);
        lstm_stage<<<128, 256>>>(H(1, par ^ 1), eWx + 1 * WSZ, 1024, H(2, par), eWh + 1 * WSZ,
                                 eWc + 1 * 4096, eb + 1 * 4096, cb + 2 * HS, H(2, par ^ 1), (float*)0);
        par ^= 1;
    }
    // -------- decoder: 64 steps x 3 layers; layer0 input = previous top h --------
    for (int t = 0; t < 64; ++t) {
        lstm_stage<<<128, 256>>>(H(2, par), dWx + 0 * WSZ, 1024, H(0, par), dWh + 0 * WSZ,
                                 dWc + 0 * 4096, db + 0 * 4096, cb + 0 * HS, H(0, par ^ 1), (float*)0);
        lstm_stage<<<128, 256>>>(H(0, par ^ 1), dWx + 1 * WSZ, 1024, H(1, par), dWh + 1 * WSZ,
                                 dWc + 1 * 4096, db + 1 * 4096, cb + 1 * HS, H(1, par ^ 1), (float*)0);
        lstm_stage<<<128, 256>>>(H(1, par ^ 1), dWx + 2 * WSZ, 1024, H(2, par), dWh + 2 * WSZ,
                                 dWc + 2 * 4096, db + 2 * 4096, cb + 2 * HS, H(2, par ^ 1),
                                 ob + (size_t)t * HS);
        par ^= 1;
    }

    final_proj<<<dim3(4, 64), 256>>>(ob, fW, fb, (float*)d_out);
}

// round 16
// speedup vs baseline: 1.5273x; 1.4685x over previous
#include <cuda_runtime.h>
#include <cstdint>
#include <cstddef>

typedef unsigned long long U64;

#define KC 32

// ---------------- persistent device scratch ----------------
__device__ float g_xT[64 * 256 * 64];        // [t][d][b]   4 MB
__device__ float g_h[3 * 1024 * 64];         // [layer][hcol][b]
__device__ float g_c[3 * 1024 * 64];         // [layer][hcol][b]
__device__ float g_z[4 * 4096 * 64];         // [quarter][gatecol][b] 4 MB
__device__ float g_outs[64 * 1024 * 64];     // [t][hcol][b] 16 MB

// ---------------- helpers ----------------
__device__ __forceinline__ U64 dupf(float x) {
    U64 r; unsigned u = __float_as_uint(x);
    asm("mov.b64 %0, {%1, %1};" : "=l"(r) : "r"(u));
    return r;
}
__device__ __forceinline__ U64 fma2(U64 a, U64 b, U64 c) {
    U64 d; asm("fma.rn.f32x2 %0, %1, %2, %3;" : "=l"(d) : "l"(a), "l"(b), "l"(c));
    return d;
}
__device__ __forceinline__ void unpk(U64 v, float& lo, float& hi) {
    unsigned a, b;
    asm("mov.b64 {%0, %1}, %2;" : "=r"(a), "=r"(b) : "l"(v));
    lo = __uint_as_float(a); hi = __uint_as_float(b);
}
__device__ __forceinline__ void cpa16(uint32_t s, const void* g) {
    asm volatile("cp.async.cg.shared.global [%0], [%1], 16;" :: "r"(s), "l"(g));
}
__device__ __forceinline__ float sigm(float x) { return 1.f / (1.f + expf(-x)); }

// ---------------- pre-transforms ----------------
// x [b][t][d] -> xT [t][d][b]
__global__ void transpose_x(const float* __restrict__ x, float* __restrict__ xT) {
    int idx = blockIdx.x * 256 + threadIdx.x;    // 1,048,576
    int b = idx >> 14, t = (idx >> 8) & 63, d = idx & 255;
    xT[((size_t)t * 256 + d) * 64 + b] = x[idx];
}

// h0/c0 [L][1][1024] broadcast into transposed state buffers
__global__ void init_hc(const float* __restrict__ h0, const float* __restrict__ c0,
                        float* __restrict__ hb, float* __restrict__ cb) {
    int idx = blockIdx.x * 256 + threadIdx.x;    // 3*1024*64 = 196608
    int l = idx >> 16, rem = idx & 65535, k = rem >> 6;
    hb[idx] = h0[l * 1024 + k];
    cb[idx] = c0[l * 1024 + k];
}

// ---------------- GEMM stage (split-K = 4) ----------------
// Computes partial z[col][row] = sum_{k in quarter} a[k][row] * W[k][col]
// over two k-segments (a0/w0 length K0, then a1/w1 length 1024).
// grid (64 col-tiles of 64 gate-cols, 4 K-quarters), 256 threads.
// Thread: 2 adjacent gate-cols x 8 rows -> 8 packed f32x2 accumulators.
__global__ void __launch_bounds__(256, 2) lstm_gemm(
    const float* __restrict__ a0, const float* __restrict__ w0, int K0,
    const float* __restrict__ a1, const float* __restrict__ w1,
    float* __restrict__ zp)
{
    __shared__ __align__(16) float As[3][KC][64];   // [buf][k][row]     24 KB
    __shared__ __align__(16) float Ws[3][KC][64];   // [buf][k][localcol] 24 KB

    const int tid = threadIdx.x;
    const int blk = blockIdx.x;       // col tile: gate-cols per gate = blk*16..+15
    const int q   = blockIdx.y;       // K quarter
    const int c2  = tid & 31;         // local col pair (cols 2c2, 2c2+1)
    const int rg  = tid >> 5;         // row group (8 rows)
    const int nq  = (K0 + 1024) >> 7; // chunks per quarter (10 or 16)
    const int base = q * nq;

    uint32_t sA = (uint32_t)__cvta_generic_to_shared(&As[0][0][0]);
    uint32_t sW = (uint32_t)__cvta_generic_to_shared(&Ws[0][0][0]);

    U64 a00 = 0, a01 = 0, a02 = 0, a03 = 0;   // col 2c2,   rows rg*8..+7
    U64 a10 = 0, a11 = 0, a12 = 0, a13 = 0;   // col 2c2+1, rows rg*8..+7

    auto issue = [&](int ch, int buf) {
        int kb = (base + ch) << 5;
        const float* ab; const float* wb; int kk0;
        if (kb < K0) { ab = a0; wb = w0; kk0 = kb; }
        else         { ab = a1; wb = w1; kk0 = kb - K0; }
        // A tile: 32k x 64 rows = 512 x 16B chunks -> 2 per thread
        #pragma unroll
        for (int j = 0; j < 2; ++j) {
            int i = tid + j * 256;
            int k = i >> 4, m4 = (i & 15) << 2;
            cpa16(sA + (uint32_t)((buf * KC * 64 + k * 64 + m4) * 4),
                  ab + (size_t)(kk0 + k) * 64 + m4);
        }
        // W tile: 32k x 64 cols (4 gates x 16 hcols) = 512 x 16B -> 2 per thread
        #pragma unroll
        for (int j = 0; j < 2; ++j) {
            int i = tid + j * 256;
            int k = i >> 4, s = i & 15, g = s >> 2, off = (s & 3) << 2;
            cpa16(sW + (uint32_t)((buf * KC * 64 + k * 64 + g * 16 + off) * 4),
                  wb + (size_t)(kk0 + k) * 4096 + (size_t)g * 1024 + blk * 16 + off);
        }
        asm volatile("cp.async.commit_group;");
    };

    issue(0, 0);
    issue(1, 1);

    for (int ch = 0; ch < nq; ++ch) {
        if (ch + 1 < nq) asm volatile("cp.async.wait_group 1;");
        else             asm volatile("cp.async.wait_group 0;");
        __syncthreads();
        if (ch + 2 < nq) issue(ch + 2, (ch + 2) % 3);

        const int buf = ch % 3;
        #pragma unroll
        for (int kk = 0; kk < KC; ++kk) {
            U64 wp = *(const U64*)&Ws[buf][kk][c2 * 2];
            float wl, wh; unpk(wp, wl, wh);
            U64 w0d = dupf(wl), w1d = dupf(wh);
            ulonglong2 av  = *(const ulonglong2*)&As[buf][kk][rg * 8];
            ulonglong2 av2 = *(const ulonglong2*)&As[buf][kk][rg * 8 + 4];
            a00 = fma2(av.x,  w0d, a00);
            a01 = fma2(av.y,  w0d, a01);
            a02 = fma2(av2.x, w0d, a02);
            a03 = fma2(av2.y, w0d, a03);
            a10 = fma2(av.x,  w1d, a10);
            a11 = fma2(av.y,  w1d, a11);
            a12 = fma2(av2.x, w1d, a12);
            a13 = fma2(av2.y, w1d, a13);
        }
        __syncthreads();
    }

    // store partials: global col G = (c>>4)*1024 + blk*16 + (c&15)
    int col0 = c2 * 2;
    int G0 = (col0 >> 4) * 1024 + blk * 16 + (col0 & 15);
    float* p = zp + (size_t)q * 4096 * 64;
    U64* p0 = (U64*)(p + (size_t)G0 * 64 + rg * 8);
    U64* p1 = (U64*)(p + (size_t)(G0 + 1) * 64 + rg * 8);
    p0[0] = a00; p0[1] = a01; p0[2] = a02; p0[3] = a03;
    p1[0] = a10; p1[1] = a11; p1[2] = a12; p1[3] = a13;
}

// ---------------- reduce + cell update ----------------
// gate order (f, i, g, o); peephole Wc on ALL 4 gates (reference quirk).
__global__ void __launch_bounds__(256) lstm_cell(
    const float* __restrict__ zp, const float* __restrict__ wc,
    const float* __restrict__ bias, float* __restrict__ cst,
    float* __restrict__ hout, float* __restrict__ outdup)
{
    int idx = blockIdx.x * 256 + threadIdx.x;   // 65536 = 1024 hcols x 64 rows
    int hcol = idx >> 6, row = idx & 63;

    float z[4];
    #pragma unroll
    for (int g = 0; g < 4; ++g) {
        size_t o = (size_t)(g * 1024 + hcol) * 64 + row;
        z[g] = zp[o] + zp[262144 + o] + zp[2 * 262144 + o] + zp[3 * 262144 + o];
    }
    float cv = cst[idx];
    float fg = sigm (z[0] + bias[hcol]        + wc[hcol]        * cv);
    float ig = sigm (z[1] + bias[1024 + hcol] + wc[1024 + hcol] * cv);
    float gg = tanhf(z[2] + bias[2048 + hcol] + wc[2048 + hcol] * cv);
    float og = sigm (z[3] + bias[3072 + hcol] + wc[3072 + hcol] * cv);
    float cn = fg * cv + ig * gg;
    float hv = og * tanhf(cn);
    cst[idx]  = cn;
    hout[idx] = hv;
    if (outdup) outdup[idx] = hv;
}

// ---------------- final projection ----------------
// out[t][b][d] = sigmoid( sum_k outs[t][k][b] * finW[k][d] + finb[d] )
__global__ void __launch_bounds__(256, 1) final_proj(
    const float* __restrict__ outs, const float* __restrict__ W,
    const float* __restrict__ bvec, float* __restrict__ out)
{
    __shared__ __align__(16) float Ash[KC][64];
    __shared__ __align__(16) float Wsh[KC][64];
    const int t = blockIdx.y, dq = blockIdx.x;
    const int tid = threadIdx.x;
    const int dc = tid & 63, rg = tid >> 6;
    const float* abase = outs + (size_t)t * 65536;

    U64 acc[8];
    #pragma unroll
    for (int qq = 0; qq < 8; ++qq) acc[qq] = 0;

    for (int kb = 0; kb < 1024; kb += KC) {
        __syncthreads();
        #pragma unroll
        for (int j = 0; j < 2; ++j) {
            int i = tid + j * 256;
            int k = i >> 4, m4 = (i & 15) << 2;
            *(float4*)&Ash[k][m4] = *(const float4*)(abase + (size_t)(kb + k) * 64 + m4);
            *(float4*)&Wsh[k][m4] = *(const float4*)(W + (size_t)(kb + k) * 256 + dq * 64 + m4);
        }
        __syncthreads();
        #pragma unroll
        for (int k = 0; k < KC; ++k) {
            U64 wd = dupf(Wsh[k][dc]);
            const ulonglong2* ap = (const ulonglong2*)&Ash[k][rg * 16];
            #pragma unroll
            for (int qq = 0; qq < 4; ++qq) {
                ulonglong2 u = ap[qq];
                acc[2 * qq]     = fma2(u.x, wd, acc[2 * qq]);
                acc[2 * qq + 1] = fma2(u.y, wd, acc[2 * qq + 1]);
            }
        }
    }

    int dg = dq * 64 + dc;
    float bb = bvec[dg];
    #pragma unroll
    for (int qq = 0; qq < 8; ++qq) {
        float lo, hi; unpk(acc[qq], lo, hi);
        int r0 = rg * 16 + 2 * qq;
        out[((size_t)t * 64 + r0)     * 256 + dg] = sigm(lo + bb);
        out[((size_t)t * 64 + r0 + 1) * 256 + dg] = sigm(hi + bb);
    }
}

// ---------------- host driver ----------------
extern "C" void kernel_launch(void* const* d_in, const int* in_sizes, int n_in,
                              void* d_out, int out_size)
{
    const float* x    = (const float*)d_in[0];
    const float* eWx0 = (const float*)d_in[1];
    const float* eWh0 = (const float*)d_in[2];
    const float* eWc0 = (const float*)d_in[3];
    const float* eb0  = (const float*)d_in[4];
    const float* eWx  = (const float*)d_in[5];
    const float* eWh  = (const float*)d_in[6];
    const float* eWc  = (const float*)d_in[7];
    const float* eb   = (const float*)d_in[8];
    const float* dWx  = (const float*)d_in[9];
    const float* dWh  = (const float*)d_in[10];
    const float* dWc  = (const float*)d_in[11];
    const float* db   = (const float*)d_in[12];
    const float* fW   = (const float*)d_in[13];
    const float* fb   = (const float*)d_in[14];
    const float* h0   = (const float*)d_in[15];
    const float* c0   = (const float*)d_in[16];

    float *xT, *hb, *cb, *zb, *ob;
    cudaGetSymbolAddress((void**)&xT, g_xT);
    cudaGetSymbolAddress((void**)&hb, g_h);
    cudaGetSymbolAddress((void**)&cb, g_c);
    cudaGetSymbolAddress((void**)&zb, g_z);
    cudaGetSymbolAddress((void**)&ob, g_outs);

    transpose_x<<<4096, 256>>>(x, xT);
    init_hc<<<768, 256>>>(h0, c0, hb, cb);

    const size_t HS  = 65536;                 // 1024 * 64
    const size_t WSZ = 1024ull * 4096;
    float* H0 = hb;
    float* H1 = hb + HS;
    float* H2 = hb + 2 * HS;
    const dim3 gg(64, 4);

    // -------- encoder: 64 steps x 3 layers --------
    for (int t = 0; t < 64; ++t) {
        const float* xin = xT + (size_t)t * 256 * 64;
        lstm_gemm<<<gg, 256>>>(xin, eWx0, 256, H0, eWh0, zb);
        lstm_cell<<<256, 256>>>(zb, eWc0, eb0, cb, H0, (float*)0);

        lstm_gemm<<<gg, 256>>>(H0, eWx, 1024, H1, eWh, zb);
        lstm_cell<<<256, 256>>>(zb, eWc, eb, cb + HS, H1, (float*)0);

        lstm_gemm<<<gg, 256>>>(H1, eWx + WSZ, 1024, H2, eWh + WSZ, zb);
        lstm_cell<<<256, 256>>>(zb, eWc + 4096, eb + 4096, cb + 2 * HS, H2, (float*)0);
    }
    // -------- decoder: 64 steps x 3 layers; layer0 input = previous top h --------
    for (int t = 0; t < 64; ++t) {
        lstm_gemm<<<gg, 256>>>(H2, dWx, 1024, H0, dWh, zb);
        lstm_cell<<<256, 256>>>(zb, dWc, db, cb, H0, (float*)0);

        lstm_gemm<<<gg, 256>>>(H0, dWx + WSZ, 1024, H1, dWh + WSZ, zb);
        lstm_cell<<<256, 256>>>(zb, dWc + 4096, db + 4096, cb + HS, H1, (float*)0);

        lstm_gemm<<<gg, 256>>>(H1, dWx + 2 * WSZ, 1024, H2, dWh + 2 * WSZ, zb);
        lstm_cell<<<256, 256>>>(zb, dWc + 2 * 4096, db + 2 * 4096, cb + 2 * HS, H2,
                                ob + (size_t)t * HS);
    }

    final_proj<<<dim3(4, 64), 256>>>(ob, fW, fb, (float*)d_out);
}